// round 11
// baseline (speedup 1.0000x reference)
#include <cuda_runtime.h>
#include <cuda_bf16.h>
#include <math.h>

#define B 32
#define P 32768
#define O 32
#define NCH 16                  // chunks per batch in match kernel (P / 2048)
#define PPB 2048                // priors per block
#define MTPB 512                // match threads per block (4 priors/thread)
#define THRESH 0.35f
#define LBLK 128                // loss blocks per batch
#define NPART (LBLK * B)        // 4096 partial slots
#define HBINS 8192              // 13-bit prefix histogram bins per batch
#define CAP 8192                // boundary-bin candidate buffer per batch
#define NSB 8                   // selB blocks per batch
#define SLICE (P / NSB)         // 4096 elements per selB block

// ---------------- scratch (static device globals; no allocation) ----------------
__device__ float2   g_bt  [B * P];        // (iou, idx-as-float) per (b,p)
__device__ __align__(16) float    g_mine[B * P];       // pos ? 0 : ce
__device__ __align__(16) unsigned g_hist[B * HBINS];   // 13-bit-prefix histogram
__device__ unsigned g_cand[B * CAP];
__device__ int      g_bp_k[B * O * NCH];
__device__ int      g_bp_p[B * O * NCH];
__device__ int      g_num_pos[B];
__device__ float    g_part_l[NPART];
__device__ float    g_part_c[NPART];
__device__ double   g_psum[B * NSB];
__device__ double   g_neg_b[B];
__device__ unsigned g_sel [B];            // published (bin<<15)|kk per batch
// monotonic ticket counters (never reset; modulo detection survives graph replays)
__device__ unsigned g_cntM[B];
__device__ unsigned g_cntL[B];
__device__ unsigned g_cnt2[B];
__device__ unsigned g_done;
__device__ unsigned g_ccnt[B];            // candidate count (reset by loss last block)

// ---------------- K1: match (IoU argmaxes) + fused forced-match fix ----------------
// grid (NCH, B), 512 threads, 4 priors per thread (stride 512).
__global__ void __launch_bounds__(MTPB) match_kernel(const float* __restrict__ priors,
                                                     const float* __restrict__ targets) {
    const int b     = blockIdx.y;
    const int chunk = blockIdx.x;
    const int tid   = threadIdx.x;
    const int lane  = tid & 31;
    const int wid   = tid >> 5;                 // 16 warps

    __shared__ float s_tx0[O], s_ty0[O], s_tx1[O], s_ty1[O], s_ta[O];
    __shared__ int   s_wk[O][16];
    __shared__ int   s_wp[O][16];
    __shared__ int   s_last;
    __shared__ int   s_bpi[O];

    // zero this launch's 2KB hist slice (1MB spread over 512 blocks)
    if (tid < 128) {
        uint4* hz = reinterpret_cast<uint4*>(g_hist) + (size_t)(b * NCH + chunk) * 128;
        hz[tid] = make_uint4(0u, 0u, 0u, 0u);
    }
    if (chunk == 0 && tid == 0) g_num_pos[b] = 0;

    if (tid < O) {
        const float* t = targets + (size_t)(b * O + tid) * 5;
        float x0 = t[0], y0 = t[1], x1 = t[2], y1 = t[3];
        s_tx0[tid] = x0; s_ty0[tid] = y0; s_tx1[tid] = x1; s_ty1[tid] = y1;
        s_ta[tid] = __fmul_rn(__fsub_rn(x1, x0), __fsub_rn(y1, y0));
    }
    __syncthreads();

    const int p0 = chunk * PPB + tid;

    float px0[4], py0[4], px1[4], py1[4], pa[4];
#pragma unroll
    for (int j = 0; j < 4; ++j) {
        float4 pr = reinterpret_cast<const float4*>(priors)[p0 + j * MTPB];
        float hw = __fmul_rn(pr.z, 0.5f);
        float hh = __fmul_rn(pr.w, 0.5f);
        px0[j] = __fsub_rn(pr.x, hw);
        py0[j] = __fsub_rn(pr.y, hh);
        px1[j] = __fadd_rn(pr.x, hw);
        py1[j] = __fadd_rn(pr.y, hh);
        pa[j]  = __fmul_rn(__fsub_rn(px1[j], px0[j]), __fsub_rn(py1[j], py0[j]));
    }

    // packed best-truth key per prior: (q_bits & ~31)|(31-o), SIGNED compares.
    // negative q -> negative int key -> always loses. init = (q=0, o=0) = 31.
    int bk[4];
#pragma unroll
    for (int j = 0; j < 4; ++j) bk[j] = 31;

    for (int o = 0; o < O; ++o) {
        const float tx0 = s_tx0[o], ty0 = s_ty0[o], tx1 = s_tx1[o], ty1 = s_ty1[o], ta = s_ta[o];
        const int oc = 31 - o;
        int ck = 3;                              // (q=0, slot=0)
#pragma unroll
        for (int j = 0; j < 4; ++j) {
            float wx = fminf(px1[j], tx1) - fmaxf(px0[j], tx0);
            float wy = fminf(py1[j], ty1) - fmaxf(py0[j], ty0);
            float in_ = fmaxf(wx, 0.0f) * wy;    // wy<0 => negative key, loses
            float un  = (pa[j] + ta) - in_;
            float q   = __fdividef(in_, un);
            int qb = __float_as_int(q);
            bk[j] = max(bk[j], (qb & (int)0xFFFFFFE0) | oc);        // first-o on tie
            ck    = max(ck,    (qb & (int)0xFFFFFFF8) | (3 - j));   // lowest p on tie
        }
        int mx = __reduce_max_sync(0xffffffffu, ck);
        unsigned bal = __ballot_sync(0xffffffffu, ck == mx);
        if (lane == 0) {
            int src = __ffs(bal) - 1;
            s_wk[o][wid] = mx;
            s_wp[o][wid] = chunk * PPB + wid * 32 + src + (3 - (mx & 7)) * MTPB;
        }
    }

    // per-prior output: recompute winner's IoU with exact IEEE ops (matches reference)
#pragma unroll
    for (int j = 0; j < 4; ++j) {
        int o = 31 - (bk[j] & 31);
        float tx0 = s_tx0[o], ty0 = s_ty0[o], tx1 = s_tx1[o], ty1 = s_ty1[o], ta = s_ta[o];
        float wx = fmaxf(__fsub_rn(fminf(px1[j], tx1), fmaxf(px0[j], tx0)), 0.0f);
        float wy = fmaxf(__fsub_rn(fminf(py1[j], ty1), fmaxf(py0[j], ty0)), 0.0f);
        float in_ = __fmul_rn(wx, wy);
        float un  = __fsub_rn(__fadd_rn(pa[j], ta), in_);
        g_bt[b * P + p0 + j * MTPB] = make_float2(__fdiv_rn(in_, un), __int_as_float(o));
    }

    __syncthreads();
    if (tid < O) {
        int o = tid;
        int ck = s_wk[o][0]; int cp = s_wp[o][0];
#pragma unroll
        for (int w = 1; w < 16; ++w) {
            int ok = s_wk[o][w]; int op = s_wp[o][w];
            if (ok > ck || (ok == ck && op < cp)) { ck = ok; cp = op; }
        }
        int idx = (b * O + o) * NCH + chunk;
        g_bp_k[idx] = ck; g_bp_p[idx] = cp;
    }

    // ---- fused fix: last chunk-block of this batch applies forced matches
    __threadfence();
    __syncthreads();
    if (tid == 0) s_last = ((atomicAdd(&g_cntM[b], 1u) % NCH) == NCH - 1);
    __syncthreads();
    if (!s_last) return;

    if (tid < O) {
        int base = (b * O + tid) * NCH;
        int ck = __ldcg(&g_bp_k[base]); int cp = __ldcg(&g_bp_p[base]);
#pragma unroll
        for (int c = 1; c < NCH; ++c) {
            int ok = __ldcg(&g_bp_k[base + c]); int op = __ldcg(&g_bp_p[base + c]);
            if (ok > ck || (ok == ck && op < cp)) { ck = ok; cp = op; }
        }
        s_bpi[tid] = cp;
    }
    __syncthreads();
    if (tid == 0) {
        // sequential, ascending o: last-wins on duplicate indices (XLA scatter order)
        for (int j = 0; j < O; ++j) {
            int p = s_bpi[j];
            g_bt[b * P + p] = make_float2(2.0f, __int_as_float(j));
        }
    }
}

// ---------------- K2: per-prior losses + hist REDs + fused boundary scan ----------------
__device__ __forceinline__ float smooth_l1(float d) {
    float ad = fabsf(d);
    return (ad < 1.0f) ? __fmul_rn(__fmul_rn(0.5f, d), d) : __fsub_rn(ad, 0.5f);
}

__global__ void __launch_bounds__(256) loss_kernel(const float* __restrict__ loc,
                                                   const float* __restrict__ conf,
                                                   const float* __restrict__ priors,
                                                   const float* __restrict__ targets) {
    const int b = blockIdx.y;
    const int p = blockIdx.x * 256 + threadIdx.x;
    const int tid = threadIdx.x;
    const int lane = tid & 31;
    const int wid  = tid >> 5;

    __shared__ float s_t[O][4];
    __shared__ float s_lab[O];
    __shared__ float s_ll[8], s_pce[8];
    __shared__ int   s_np[8];
    __shared__ int   s_last;
    __shared__ unsigned s_ws[8];
    __shared__ unsigned s_word;

    if (tid < O) {
        const float* t = targets + (size_t)(b * O + tid) * 5;
        s_t[tid][0] = t[0]; s_t[tid][1] = t[1];
        s_t[tid][2] = t[2]; s_t[tid][3] = t[3];
        s_lab[tid]  = t[4];
    }
    __syncthreads();

    const int bp = b * P + p;
    float2 bt = g_bt[bp];
    const int o = __float_as_int(bt.y);
    const int ct = (bt.x < THRESH) ? 0 : ((int)s_lab[o] + 1);
    const bool pos = (ct > 0);

    float2 cd = reinterpret_cast<const float2*>(conf)[bp];
    float m  = fmaxf(cd.x, cd.y);
    float mn = fminf(cd.x, cd.y);
    float lse = __fadd_rn(m, __logf(__fadd_rn(1.0f, __expf(__fsub_rn(mn, m)))));
    float picked = (ct == 0) ? cd.x : cd.y;
    float ce = __fsub_rn(lse, picked);

    g_mine[bp] = pos ? 0.0f : ce;
    if (!pos) {
        unsigned u = __float_as_uint(ce);
        if (u) atomicAdd(&g_hist[b * HBINS + (u >> 19)], 1u);   // spread-bin RED
    }

    unsigned bal = __ballot_sync(0xffffffffu, pos);
    float ll = 0.0f, pce = 0.0f;
    if (bal) {   // warp-uniform skip
        if (pos) {
            float4 pr = reinterpret_cast<const float4*>(priors)[p];
            float mx0 = s_t[o][0], my0 = s_t[o][1], mx1 = s_t[o][2], my1 = s_t[o][3];
            float lt0 = __fdividef(__fsub_rn(__fmul_rn(__fadd_rn(mx0, mx1), 0.5f), pr.x),
                                   __fmul_rn(0.1f, pr.z));
            float lt1 = __fdividef(__fsub_rn(__fmul_rn(__fadd_rn(my0, my1), 0.5f), pr.y),
                                   __fmul_rn(0.1f, pr.w));
            float lt2 = __fmul_rn(__logf(__fdividef(__fsub_rn(mx1, mx0), pr.z)), 5.0f);
            float lt3 = __fmul_rn(__logf(__fdividef(__fsub_rn(my1, my0), pr.w)), 5.0f);
            float4 ld = reinterpret_cast<const float4*>(loc)[bp];
            ll = __fadd_rn(__fadd_rn(smooth_l1(__fsub_rn(ld.x, lt0)),
                                     smooth_l1(__fsub_rn(ld.y, lt1))),
                           __fadd_rn(smooth_l1(__fsub_rn(ld.z, lt2)),
                                     smooth_l1(__fsub_rn(ld.w, lt3))));
            pce = ce;
        }
#pragma unroll
        for (int d = 16; d > 0; d >>= 1) {
            ll  += __shfl_down_sync(0xffffffffu, ll, d);
            pce += __shfl_down_sync(0xffffffffu, pce, d);
        }
    }
    if (lane == 0) { s_ll[wid] = ll; s_pce[wid] = pce; s_np[wid] = __popc(bal); }
    __syncthreads();
    if (tid == 0) {
        float tl = 0.0f, tc = 0.0f; int tn = 0;
#pragma unroll
        for (int w = 0; w < 8; ++w) { tl += s_ll[w]; tc += s_pce[w]; tn += s_np[w]; }
        int slot = b * LBLK + blockIdx.x;
        g_part_l[slot] = tl;
        g_part_c[slot] = tc;
        if (tn) atomicAdd(&g_num_pos[b], tn);
    }

    // ---- fused boundary scan: last loss block of this batch
    __threadfence();
    __syncthreads();
    if (tid == 0) s_last = ((atomicAdd(&g_cntL[b], 1u) % LBLK) == LBLK - 1);
    __syncthreads();
    if (!s_last) return;

    if (tid == 0) { g_ccnt[b] = 0; s_word = 0u; }       // fallback: bin=0, kk=0
    const unsigned np = (unsigned)g_num_pos[b];
    const unsigned k  = umin(7u * np, (unsigned)(P - 1));

    // scan 8192 bins descending; thread owns 32 bins
    const unsigned* hist = g_hist + (size_t)b * HBINS;
    const int start = HBINS - 32 * (tid + 1);
    unsigned L = 0;
    {
        const uint4* h4 = reinterpret_cast<const uint4*>(hist + start);
#pragma unroll
        for (int i = 0; i < 8; ++i) { uint4 v = __ldcg((const uint4*)(h4 + i)); L += v.x + v.y + v.z + v.w; }
    }
    unsigned c = L;
#pragma unroll
    for (int dd = 1; dd < 32; dd <<= 1) {
        unsigned x = __shfl_up_sync(0xffffffffu, c, dd);
        if (lane >= dd) c += x;
    }
    if (lane == 31) s_ws[wid] = c;
    __syncthreads();
    {
        unsigned off = 0;
#pragma unroll
        for (int w = 0; w < 8; ++w) off += (w < wid) ? s_ws[w] : 0u;
        unsigned Pex = c + off - L;
        if (k > 0 && Pex < k && Pex + L >= k) {
            unsigned cc = Pex;
            for (int j = 31; j >= 0; --j) {
                unsigned h = __ldcg(&hist[start + j]);
                cc += h;
                if (cc >= k) { s_word = ((unsigned)(start + j) << 15) | (k - (cc - h)); break; }
            }
        }
    }
    __syncthreads();
    if (tid == 0) g_sel[b] = s_word;
}

// ---------------- K3: selB — sweep + ticketed refine/finalize ----------------
__global__ void __launch_bounds__(512) selB_kernel(float* __restrict__ out) {
    const int sb  = blockIdx.x;
    const int b   = blockIdx.y;
    const int tid = threadIdx.x;
    const int lane = tid & 31;
    const int wid  = tid >> 5;

    __shared__ unsigned s_h[1024];
    __shared__ unsigned s_ws[16];
    __shared__ int      s_last, s_fin;
    __shared__ double   s_red[16];
    __shared__ unsigned long long s_m[16];
    __shared__ unsigned s_b1, s_k3, s_b0, s_k4;

    const unsigned np = (unsigned)g_num_pos[b];
    const unsigned k  = umin(7u * np, (unsigned)(P - 1));
    const unsigned word = g_sel[b];
    const unsigned bin  = word >> 15;
    const unsigned kk2  = word & 0x7FFFu;

    // slice sweep: above-bin sum + candidate emission
    unsigned d[8];
    {
        const uint4* m4 = reinterpret_cast<const uint4*>(g_mine + (size_t)b * P + sb * SLICE);
        uint4 x0 = m4[tid], x1 = m4[tid + 512];
        d[0] = x0.x; d[1] = x0.y; d[2] = x0.z; d[3] = x0.w;
        d[4] = x1.x; d[5] = x1.y; d[6] = x1.z; d[7] = x1.w;
    }
    double fs = 0.0;
#pragma unroll
    for (int e = 0; e < 8; ++e) {
        unsigned u = d[e];
        unsigned hi = u >> 19;
        if (hi > bin) fs += (double)__uint_as_float(u);
        bool isc = (u != 0u) && (hi == bin);
        unsigned bal = __ballot_sync(0xffffffffu, isc);
        if (bal) {
            unsigned base = 0;
            int leader = __ffs(bal) - 1;
            if (lane == leader) base = atomicAdd(&g_ccnt[b], (unsigned)__popc(bal));
            base = __shfl_sync(0xffffffffu, base, leader);
            if (isc) {
                unsigned idx = base + (unsigned)__popc(bal & ((1u << lane) - 1u));
                if (idx < CAP) g_cand[b * CAP + idx] = u;
            }
        }
    }
#pragma unroll
    for (int dd = 16; dd > 0; dd >>= 1) fs += __shfl_down_sync(0xffffffffu, fs, dd);
    if (lane == 0) s_red[wid] = fs;
    __syncthreads();
    if (tid == 0) {
        double t = 0.0;
#pragma unroll
        for (int j = 0; j < 16; ++j) t += s_red[j];
        g_psum[b * NSB + sb] = t;
        __threadfence();
        s_last = ((atomicAdd(&g_cnt2[b], 1u) % NSB) == NSB - 1);
    }
    __syncthreads();
    if (!s_last) return;

    // ---- last block of this batch: exact refine within boundary bin
    const unsigned m = umin(__ldcg(&g_ccnt[b]), (unsigned)CAP);
    const unsigned* cand = g_cand + b * CAP;

    // pass 1: bits [18:9] (1024 bins), thread owns 2 descending bins
    if (tid < 512) { s_h[tid] = 0; s_h[tid + 512] = 0; }
    if (tid == 0) { s_b1 = 0; s_k3 = 0; }
    __syncthreads();
    for (unsigned i = tid; i < m; i += 512)
        atomicAdd(&s_h[(__ldcg(&cand[i]) >> 9) & 1023u], 1u);
    __syncthreads();
    {
        unsigned vh = s_h[1023 - 2 * tid], vl = s_h[1022 - 2 * tid];
        unsigned Lr = vh + vl;
        unsigned cr = Lr;
#pragma unroll
        for (int dd = 1; dd < 32; dd <<= 1) {
            unsigned x = __shfl_up_sync(0xffffffffu, cr, dd);
            if (lane >= dd) cr += x;
        }
        if (lane == 31) s_ws[wid] = cr;
        __syncthreads();
        unsigned off = 0;
#pragma unroll
        for (int w = 0; w < 16; ++w) off += (w < wid) ? s_ws[w] : 0u;
        cr += off;
        unsigned Pex = cr - Lr;
        if (kk2 > 0 && Pex < kk2 && cr >= kk2) {
            if (Pex + vh >= kk2) { s_b1 = 1023u - 2 * tid; s_k3 = kk2 - Pex; }
            else                 { s_b1 = 1022u - 2 * tid; s_k3 = kk2 - (Pex + vh); }
        }
    }
    __syncthreads();
    const unsigned b1 = s_b1, kk3 = s_k3;

    // pass 2: bits [8:0] (512 bins)
    if (tid < 512) s_h[tid] = 0;
    if (tid == 0) { s_b0 = 0; s_k4 = 0; }
    __syncthreads();
    for (unsigned i = tid; i < m; i += 512) {
        unsigned u = __ldcg(&cand[i]);
        if (((u >> 9) & 1023u) == b1) atomicAdd(&s_h[u & 511u], 1u);
    }
    __syncthreads();
    {
        unsigned v = s_h[511 - tid];
        unsigned cr = v;
#pragma unroll
        for (int dd = 1; dd < 32; dd <<= 1) {
            unsigned x = __shfl_up_sync(0xffffffffu, cr, dd);
            if (lane >= dd) cr += x;
        }
        if (lane == 31) s_ws[wid] = cr;
        __syncthreads();
        unsigned off = 0;
#pragma unroll
        for (int w = 0; w < 16; ++w) off += (w < wid) ? s_ws[w] : 0u;
        cr += off;
        unsigned Pex = cr - v;
        if (kk3 > 0 && Pex < kk3 && cr >= kk3) { s_b0 = 511u - tid; s_k4 = kk3 - Pex; }
    }
    __syncthreads();
    const unsigned T   = (bin << 19) | (b1 << 9) | s_b0;
    const unsigned kk4 = s_k4;

    // exact in-bin sum via shared-exponent integer mantissas (order-independent)
    const unsigned e8 = bin >> 4;
    const unsigned implicit = e8 ? 0x800000u : 0u;
    unsigned long long ms = 0ull;
    for (unsigned i = tid; i < m; i += 512) {
        unsigned u = __ldcg(&cand[i]);
        if (u > T) ms += (unsigned long long)((u & 0x7FFFFFu) | implicit);
    }
#pragma unroll
    for (int dd = 16; dd > 0; dd >>= 1) ms += __shfl_down_sync(0xffffffffu, ms, dd);
    if (lane == 0) s_m[wid] = ms;
    __syncthreads();
    if (tid == 0) {
        unsigned long long mt = 0ull;
#pragma unroll
        for (int j = 0; j < 16; ++j) mt += s_m[j];
        double din = ldexp((double)mt, e8 ? ((int)e8 - 150) : -149);
        double tot = 0.0;
#pragma unroll
        for (int j = 0; j < NSB; ++j) tot += __ldcg(&g_psum[b * NSB + j]);
        tot += din + (double)kk4 * (double)__uint_as_float(T);
        g_neg_b[b] = (k > 0) ? tot : 0.0;
        __threadfence();
        s_fin = ((atomicAdd(&g_done, 1u) % B) == B - 1);
    }
    __syncthreads();
    if (!s_fin) return;

    // ---- global finalize (last batch to finish)
    double l = 0.0, cc2 = 0.0;
#pragma unroll
    for (int it = 0; it < NPART / 512; ++it) {
        l   += (double)g_part_l[tid + it * 512];
        cc2 += (double)g_part_c[tid + it * 512];
    }
#pragma unroll
    for (int dd = 16; dd > 0; dd >>= 1) {
        l   += __shfl_down_sync(0xffffffffu, l, dd);
        cc2 += __shfl_down_sync(0xffffffffu, cc2, dd);
    }
    __shared__ double s_l2[16], s_c2[16];
    if (lane == 0) { s_l2[wid] = l; s_c2[wid] = cc2; }
    __syncthreads();
    if (tid == 0) {
        double tl = 0.0, tc = 0.0;
#pragma unroll
        for (int j = 0; j < 16; ++j) { tl += s_l2[j]; tc += s_c2[j]; }
        double tneg = 0.0;
        int s = 0;
#pragma unroll
        for (int j = 0; j < B; ++j) {
            tneg += __ldcg(&g_neg_b[j]);
            s += g_num_pos[j];
        }
        double N = (double)s;
        if (N < 1.0) N = 1.0;
        out[0] = (float)(tl / N);
        out[1] = (float)((tc + tneg) / N);
    }
}

// ---------------- launch ----------------
extern "C" void kernel_launch(void* const* d_in, const int* in_sizes, int n_in,
                              void* d_out, int out_size) {
    const float* loc     = (const float*)d_in[0];
    const float* conf    = (const float*)d_in[1];
    const float* priors  = (const float*)d_in[2];
    const float* targets = (const float*)d_in[3];
    float* out = (float*)d_out;

    match_kernel<<<dim3(NCH, B), MTPB>>>(priors, targets);
    loss_kernel<<<dim3(LBLK, B), 256>>>(loc, conf, priors, targets);
    selB_kernel<<<dim3(NSB, B), 512>>>(out);
}

// round 13
// speedup vs baseline: 1.3040x; 1.3040x over previous
#include <cuda_runtime.h>
#include <cuda_bf16.h>
#include <math.h>

#define B 32
#define P 32768
#define O 32
#define NCH 16                  // chunks per batch in match kernel (P / 2048)
#define PPB 2048                // priors per block
#define THRESH 0.35f
#define LBLK 128                // loss blocks per batch
#define NPART (LBLK * B)        // 4096 partial slots
#define HBINS 8192              // 13-bit prefix histogram bins per batch
#define CAP 8192                // boundary-bin candidate buffer per batch
#define NSB 8                   // selA/selB blocks per batch
#define SLICE (P / NSB)         // 4096 elements per block

// ---------------- scratch (static device globals; no allocation) ----------------
__device__ float2   g_bt  [B * P];        // (iou, idx-as-float) per (b,p)
__device__ __align__(16) float    g_mine[B * P];       // pos ? 0 : ce
__device__ __align__(16) unsigned g_hist[B * HBINS];   // 13-bit-prefix histogram
__device__ unsigned g_cand[B * CAP];
__device__ int      g_bp_k[B * O * NCH];
__device__ int      g_bp_p[B * O * NCH];
__device__ int      g_num_pos[B];
__device__ float    g_part_l[NPART];
__device__ float    g_part_c[NPART];
__device__ double   g_psum[B * NSB];
__device__ double   g_neg_b[B];
__device__ unsigned g_sel [B];            // published (bin<<15)|kk per batch
// monotonic ticket counters (never reset; modulo detection survives graph replays)
__device__ unsigned g_cntM[B];
__device__ unsigned g_cntA[B];
__device__ unsigned g_cnt2[B];
__device__ unsigned g_done;
__device__ unsigned g_ccnt[B];            // candidate count (reset by selA last block)

// ---------------- K1: match (IoU argmaxes, signed keys, divide-by-S) + fused fix ----------------
// grid (NCH, B), 256 threads, 8 priors per thread (stride 256).
__global__ void __launch_bounds__(256) match_kernel(const float* __restrict__ priors,
                                                    const float* __restrict__ targets) {
    const int b     = blockIdx.y;
    const int chunk = blockIdx.x;
    const int tid   = threadIdx.x;
    const int lane  = tid & 31;
    const int wid   = tid >> 5;                 // 8 warps

    __shared__ float4 s_t4[O];                  // (-tx0, -ty0, tx1, ty1)
    __shared__ float  s_ta[O];
    __shared__ int    s_wk[O][8];
    __shared__ int    s_wp[O][8];
    __shared__ int    s_last;
    __shared__ int    s_bpi[O];

    // zero this launch's 2KB hist slice (1MB spread over 512 blocks)
    if (tid < 128) {
        uint4* hz = reinterpret_cast<uint4*>(g_hist) + (size_t)(b * NCH + chunk) * 128;
        hz[tid] = make_uint4(0u, 0u, 0u, 0u);
    }
    if (chunk == 0 && tid == 0) g_num_pos[b] = 0;

    if (tid < O) {
        const float* t = targets + (size_t)(b * O + tid) * 5;
        float x0 = t[0], y0 = t[1], x1 = t[2], y1 = t[3];
        s_t4[tid] = make_float4(-x0, -y0, x1, y1);
        s_ta[tid] = __fmul_rn(__fsub_rn(x1, x0), __fsub_rn(y1, y0));
    }
    __syncthreads();

    const int p0 = chunk * PPB + tid;

    // prior geometry (negated mins so width = min+min add-form)
    float px1[8], nx0[8], py1[8], ny0[8], pa[8];
#pragma unroll
    for (int j = 0; j < 8; ++j) {
        float4 pr = reinterpret_cast<const float4*>(priors)[p0 + j * 256];
        float hw = __fmul_rn(pr.z, 0.5f);
        float hh = __fmul_rn(pr.w, 0.5f);
        float x0 = __fsub_rn(pr.x, hw);
        float y0 = __fsub_rn(pr.y, hh);
        px1[j] = __fadd_rn(pr.x, hw);
        py1[j] = __fadd_rn(pr.y, hh);
        nx0[j] = -x0;
        ny0[j] = -y0;
        pa[j]  = __fmul_rn(__fsub_rn(px1[j], x0), __fsub_rn(py1[j], y0));
    }

    // packed best-truth key per prior: (q_bits & ~31)|(31-o), SIGNED compares.
    // q' = in/S (monotone in q = in/un); negative q' -> negative key -> loses.
    int bk[8];
#pragma unroll
    for (int j = 0; j < 8; ++j) bk[j] = 31;

    for (int o = 0; o < O; ++o) {
        const float4 t4 = s_t4[o];              // (ntx0, nty0, tx1, ty1)
        const float  ta = s_ta[o];
        const int oc = 31 - o;
        int ck = 7;                             // (q=0, slot 0)
#pragma unroll
        for (int j = 0; j < 8; ++j) {
            float wx = fminf(px1[j], t4.z) + fminf(nx0[j], t4.x);
            float wy = fminf(py1[j], t4.w) + fminf(ny0[j], t4.y);
            float in_ = fmaxf(wx, 0.0f) * wy;   // wy<0 => q'<=-0 => negative key
            float S   = pa[j] + ta;             // > 0 always
            float q   = __fdividef(in_, S);
            int qb = __float_as_int(q);
            bk[j] = max(bk[j], (qb & (int)0xFFFFFFE0) | oc);        // first-o on tie
            ck    = max(ck,    (qb & (int)0xFFFFFFF8) | (7 - j));   // lowest p on tie
        }
        int mx = __reduce_max_sync(0xffffffffu, ck);
        unsigned bal = __ballot_sync(0xffffffffu, ck == mx);
        if (lane == 0) {
            int src = __ffs(bal) - 1;
            s_wk[o][wid] = mx;
            s_wp[o][wid] = chunk * PPB + wid * 32 + src + (7 - (mx & 7)) * 256;
        }
    }

    // per-prior output: recompute winner's IoU with exact IEEE ops (matches reference)
#pragma unroll
    for (int j = 0; j < 8; ++j) {
        int o = 31 - (bk[j] & 31);
        float4 t4 = s_t4[o];
        float ta = s_ta[o];
        // a + (-b) == a - b exactly in IEEE
        float wx = fmaxf(__fadd_rn(fminf(px1[j], t4.z), fminf(nx0[j], t4.x)), 0.0f);
        float wy = fmaxf(__fadd_rn(fminf(py1[j], t4.w), fminf(ny0[j], t4.y)), 0.0f);
        float in_ = __fmul_rn(wx, wy);
        float un  = __fsub_rn(__fadd_rn(pa[j], ta), in_);
        g_bt[b * P + p0 + j * 256] = make_float2(__fdiv_rn(in_, un), __int_as_float(o));
    }

    __syncthreads();
    if (tid < O) {
        int o = tid;
        int ck = s_wk[o][0]; int cp = s_wp[o][0];
#pragma unroll
        for (int w = 1; w < 8; ++w) {
            int ok = s_wk[o][w]; int op = s_wp[o][w];
            if (ok > ck || (ok == ck && op < cp)) { ck = ok; cp = op; }
        }
        int idx = (b * O + o) * NCH + chunk;
        g_bp_k[idx] = ck; g_bp_p[idx] = cp;
    }

    // ---- fused fix: last chunk-block of this batch applies forced matches
    __threadfence();
    __syncthreads();
    if (tid == 0) s_last = ((atomicAdd(&g_cntM[b], 1u) % NCH) == NCH - 1);
    __syncthreads();
    if (!s_last) return;

    if (tid < O) {
        int base = (b * O + tid) * NCH;
        int ck = __ldcg(&g_bp_k[base]); int cp = __ldcg(&g_bp_p[base]);
#pragma unroll
        for (int c = 1; c < NCH; ++c) {
            int ok = __ldcg(&g_bp_k[base + c]); int op = __ldcg(&g_bp_p[base + c]);
            if (ok > ck || (ok == ck && op < cp)) { ck = ok; cp = op; }
        }
        s_bpi[tid] = cp;
    }
    __syncthreads();
    if (tid == 0) {
        // sequential, ascending o: last-wins on duplicates (XLA scatter order)
        for (int j = 0; j < O; ++j) {
            int p = s_bpi[j];
            g_bt[b * P + p] = make_float2(2.0f, __int_as_float(j));
        }
    }
}

// ---------------- K2: per-prior losses (atomic-free block partials, NO hist) ----------------
__device__ __forceinline__ float smooth_l1(float d) {
    float ad = fabsf(d);
    return (ad < 1.0f) ? __fmul_rn(__fmul_rn(0.5f, d), d) : __fsub_rn(ad, 0.5f);
}

__global__ void __launch_bounds__(256) loss_kernel(const float* __restrict__ loc,
                                                   const float* __restrict__ conf,
                                                   const float* __restrict__ priors,
                                                   const float* __restrict__ targets) {
    const int b = blockIdx.y;
    const int p = blockIdx.x * 256 + threadIdx.x;
    const int tid = threadIdx.x;
    const int lane = tid & 31;
    const int wid  = tid >> 5;

    __shared__ float s_t[O][4];
    __shared__ float s_lab[O];
    __shared__ float s_ll[8], s_pce[8];
    __shared__ int   s_np[8];
    if (tid < O) {
        const float* t = targets + (size_t)(b * O + tid) * 5;
        s_t[tid][0] = t[0]; s_t[tid][1] = t[1];
        s_t[tid][2] = t[2]; s_t[tid][3] = t[3];
        s_lab[tid]  = t[4];
    }
    __syncthreads();

    const int bp = b * P + p;
    float2 bt = g_bt[bp];
    const int o = __float_as_int(bt.y);
    const int ct = (bt.x < THRESH) ? 0 : ((int)s_lab[o] + 1);
    const bool pos = (ct > 0);

    float2 cd = reinterpret_cast<const float2*>(conf)[bp];
    float m  = fmaxf(cd.x, cd.y);
    float mn = fminf(cd.x, cd.y);
    float lse = __fadd_rn(m, __logf(__fadd_rn(1.0f, __expf(__fsub_rn(mn, m)))));
    float picked = (ct == 0) ? cd.x : cd.y;
    float ce = __fsub_rn(lse, picked);

    g_mine[bp] = pos ? 0.0f : ce;

    unsigned bal = __ballot_sync(0xffffffffu, pos);
    float ll = 0.0f, pce = 0.0f;
    if (bal) {   // warp-uniform skip
        if (pos) {
            float4 pr = reinterpret_cast<const float4*>(priors)[p];
            float mx0 = s_t[o][0], my0 = s_t[o][1], mx1 = s_t[o][2], my1 = s_t[o][3];
            float lt0 = __fdividef(__fsub_rn(__fmul_rn(__fadd_rn(mx0, mx1), 0.5f), pr.x),
                                   __fmul_rn(0.1f, pr.z));
            float lt1 = __fdividef(__fsub_rn(__fmul_rn(__fadd_rn(my0, my1), 0.5f), pr.y),
                                   __fmul_rn(0.1f, pr.w));
            float lt2 = __fmul_rn(__logf(__fdividef(__fsub_rn(mx1, mx0), pr.z)), 5.0f);
            float lt3 = __fmul_rn(__logf(__fdividef(__fsub_rn(my1, my0), pr.w)), 5.0f);
            float4 ld = reinterpret_cast<const float4*>(loc)[bp];
            ll = __fadd_rn(__fadd_rn(smooth_l1(__fsub_rn(ld.x, lt0)),
                                     smooth_l1(__fsub_rn(ld.y, lt1))),
                           __fadd_rn(smooth_l1(__fsub_rn(ld.z, lt2)),
                                     smooth_l1(__fsub_rn(ld.w, lt3))));
            pce = ce;
        }
#pragma unroll
        for (int d = 16; d > 0; d >>= 1) {
            ll  += __shfl_down_sync(0xffffffffu, ll, d);
            pce += __shfl_down_sync(0xffffffffu, pce, d);
        }
    }
    if (lane == 0) { s_ll[wid] = ll; s_pce[wid] = pce; s_np[wid] = __popc(bal); }
    __syncthreads();
    if (tid == 0) {
        float tl = 0.0f, tc = 0.0f; int tn = 0;
#pragma unroll
        for (int w = 0; w < 8; ++w) { tl += s_ll[w]; tc += s_pce[w]; tn += s_np[w]; }
        int slot = b * LBLK + blockIdx.x;
        g_part_l[slot] = tl;
        g_part_c[slot] = tc;
        if (tn) atomicAdd(&g_num_pos[b], tn);
    }
}

// ---------------- K3: selA — histogram build + (last block) boundary scan/publish ----------------
__global__ void __launch_bounds__(512) selA_kernel() {
    const int sb  = blockIdx.x;
    const int b   = blockIdx.y;
    const int tid = threadIdx.x;
    const int lane = tid & 31;
    const int wid  = tid >> 5;

    __shared__ unsigned s_hist[HBINS];   // 32KB
    __shared__ unsigned s_ws[16];
    __shared__ int      s_last;
    __shared__ unsigned s_word;

#pragma unroll
    for (int i = 0; i < HBINS / 512; ++i) s_hist[tid + i * 512] = 0;
    __syncthreads();

    const uint4* m4 = reinterpret_cast<const uint4*>(g_mine + (size_t)b * P + sb * SLICE);
    uint4 x0 = m4[tid], x1 = m4[tid + 512];
    unsigned d[8] = {x0.x, x0.y, x0.z, x0.w, x1.x, x1.y, x1.z, x1.w};
#pragma unroll
    for (int e = 0; e < 8; ++e)
        if (d[e]) atomicAdd(&s_hist[d[e] >> 19], 1u);
    __syncthreads();
#pragma unroll
    for (int i = 0; i < HBINS / 512; ++i) {
        unsigned v = s_hist[tid + i * 512];
        if (v) atomicAdd(&g_hist[b * HBINS + tid + i * 512], v);
    }
    __threadfence();
    __syncthreads();
    if (tid == 0) s_last = ((atomicAdd(&g_cntA[b], 1u) % NSB) == NSB - 1);
    __syncthreads();
    if (!s_last) return;

    // last block of this batch: hist complete -> scan & publish (bin<<15)|kk
    if (tid == 0) { g_ccnt[b] = 0; s_word = 0u; }        // fallback bin=0,kk=0
    const unsigned np = (unsigned)g_num_pos[b];
    const unsigned k  = umin(7u * np, (unsigned)(P - 1));
    const unsigned* hist = g_hist + (size_t)b * HBINS;
    const int start = HBINS - 16 * (tid + 1);
    unsigned L = 0;
    {
        const uint4* h4 = reinterpret_cast<const uint4*>(hist + start);
#pragma unroll
        for (int i = 0; i < 4; ++i) { uint4 v = __ldcg((const uint4*)(h4 + i)); L += v.x + v.y + v.z + v.w; }
    }
    unsigned c = L;
#pragma unroll
    for (int dd = 1; dd < 32; dd <<= 1) {
        unsigned x = __shfl_up_sync(0xffffffffu, c, dd);
        if (lane >= dd) c += x;
    }
    if (lane == 31) s_ws[wid] = c;
    __syncthreads();
    unsigned off = 0;
#pragma unroll
    for (int w = 0; w < 16; ++w) off += (w < wid) ? s_ws[w] : 0u;
    unsigned Pex = c + off - L;
    if (k > 0 && Pex < k && Pex + L >= k) {
        unsigned cc = Pex;
        for (int j = 15; j >= 0; --j) {
            unsigned h = __ldcg(&hist[start + j]);
            cc += h;
            if (cc >= k) { s_word = ((unsigned)(start + j) << 15) | (k - (cc - h)); break; }
        }
    }
    __syncthreads();
    if (tid == 0) g_sel[b] = s_word;
}

// ---------------- K4: selB — sweep + ticketed refine/finalize ----------------
__global__ void __launch_bounds__(512) selB_kernel(float* __restrict__ out) {
    const int sb  = blockIdx.x;
    const int b   = blockIdx.y;
    const int tid = threadIdx.x;
    const int lane = tid & 31;
    const int wid  = tid >> 5;

    __shared__ unsigned s_h[1024];
    __shared__ unsigned s_ws[16];
    __shared__ int      s_last, s_fin;
    __shared__ double   s_red[16];
    __shared__ unsigned long long s_m[16];
    __shared__ unsigned s_b1, s_k3, s_b0, s_k4;

    const unsigned np = (unsigned)g_num_pos[b];
    const unsigned k  = umin(7u * np, (unsigned)(P - 1));
    const unsigned word = g_sel[b];
    const unsigned bin  = word >> 15;
    const unsigned kk2  = word & 0x7FFFu;

    // slice sweep: above-bin sum + candidate emission
    unsigned d[8];
    {
        const uint4* m4 = reinterpret_cast<const uint4*>(g_mine + (size_t)b * P + sb * SLICE);
        uint4 x0 = m4[tid], x1 = m4[tid + 512];
        d[0] = x0.x; d[1] = x0.y; d[2] = x0.z; d[3] = x0.w;
        d[4] = x1.x; d[5] = x1.y; d[6] = x1.z; d[7] = x1.w;
    }
    double fs = 0.0;
#pragma unroll
    for (int e = 0; e < 8; ++e) {
        unsigned u = d[e];
        unsigned hi = u >> 19;
        if (hi > bin) fs += (double)__uint_as_float(u);
        bool isc = (u != 0u) && (hi == bin);
        unsigned bal = __ballot_sync(0xffffffffu, isc);
        if (bal) {
            unsigned base = 0;
            int leader = __ffs(bal) - 1;
            if (lane == leader) base = atomicAdd(&g_ccnt[b], (unsigned)__popc(bal));
            base = __shfl_sync(0xffffffffu, base, leader);
            if (isc) {
                unsigned idx = base + (unsigned)__popc(bal & ((1u << lane) - 1u));
                if (idx < CAP) g_cand[b * CAP + idx] = u;
            }
        }
    }
#pragma unroll
    for (int dd = 16; dd > 0; dd >>= 1) fs += __shfl_down_sync(0xffffffffu, fs, dd);
    if (lane == 0) s_red[wid] = fs;
    __syncthreads();
    if (tid == 0) {
        double t = 0.0;
#pragma unroll
        for (int j = 0; j < 16; ++j) t += s_red[j];
        g_psum[b * NSB + sb] = t;
        __threadfence();
        s_last = ((atomicAdd(&g_cnt2[b], 1u) % NSB) == NSB - 1);
    }
    __syncthreads();
    if (!s_last) return;

    // ---- last block of this batch: exact refine within boundary bin
    const unsigned m = umin(__ldcg(&g_ccnt[b]), (unsigned)CAP);
    const unsigned* cand = g_cand + b * CAP;

    // pass 1: bits [18:9] (1024 bins), thread owns 2 descending bins
    if (tid < 512) { s_h[tid] = 0; s_h[tid + 512] = 0; }
    if (tid == 0) { s_b1 = 0; s_k3 = 0; }
    __syncthreads();
    for (unsigned i = tid; i < m; i += 512)
        atomicAdd(&s_h[(__ldcg(&cand[i]) >> 9) & 1023u], 1u);
    __syncthreads();
    {
        unsigned vh = s_h[1023 - 2 * tid], vl = s_h[1022 - 2 * tid];
        unsigned Lr = vh + vl;
        unsigned cr = Lr;
#pragma unroll
        for (int dd = 1; dd < 32; dd <<= 1) {
            unsigned x = __shfl_up_sync(0xffffffffu, cr, dd);
            if (lane >= dd) cr += x;
        }
        if (lane == 31) s_ws[wid] = cr;
        __syncthreads();
        unsigned off = 0;
#pragma unroll
        for (int w = 0; w < 16; ++w) off += (w < wid) ? s_ws[w] : 0u;
        cr += off;
        unsigned Pex = cr - Lr;
        if (kk2 > 0 && Pex < kk2 && cr >= kk2) {
            if (Pex + vh >= kk2) { s_b1 = 1023u - 2 * tid; s_k3 = kk2 - Pex; }
            else                 { s_b1 = 1022u - 2 * tid; s_k3 = kk2 - (Pex + vh); }
        }
    }
    __syncthreads();
    const unsigned b1 = s_b1, kk3 = s_k3;

    // pass 2: bits [8:0] (512 bins)
    if (tid < 512) s_h[tid] = 0;
    if (tid == 0) { s_b0 = 0; s_k4 = 0; }
    __syncthreads();
    for (unsigned i = tid; i < m; i += 512) {
        unsigned u = __ldcg(&cand[i]);
        if (((u >> 9) & 1023u) == b1) atomicAdd(&s_h[u & 511u], 1u);
    }
    __syncthreads();
    {
        unsigned v = s_h[511 - tid];
        unsigned cr = v;
#pragma unroll
        for (int dd = 1; dd < 32; dd <<= 1) {
            unsigned x = __shfl_up_sync(0xffffffffu, cr, dd);
            if (lane >= dd) cr += x;
        }
        if (lane == 31) s_ws[wid] = cr;
        __syncthreads();
        unsigned off = 0;
#pragma unroll
        for (int w = 0; w < 16; ++w) off += (w < wid) ? s_ws[w] : 0u;
        cr += off;
        unsigned Pex = cr - v;
        if (kk3 > 0 && Pex < kk3 && cr >= kk3) { s_b0 = 511u - tid; s_k4 = kk3 - Pex; }
    }
    __syncthreads();
    const unsigned T   = (bin << 19) | (b1 << 9) | s_b0;
    const unsigned kk4 = s_k4;

    // exact in-bin sum via shared-exponent integer mantissas (order-independent)
    const unsigned e8 = bin >> 4;
    const unsigned implicit = e8 ? 0x800000u : 0u;
    unsigned long long ms = 0ull;
    for (unsigned i = tid; i < m; i += 512) {
        unsigned u = __ldcg(&cand[i]);
        if (u > T) ms += (unsigned long long)((u & 0x7FFFFFu) | implicit);
    }
#pragma unroll
    for (int dd = 16; dd > 0; dd >>= 1) ms += __shfl_down_sync(0xffffffffu, ms, dd);
    if (lane == 0) s_m[wid] = ms;
    __syncthreads();
    if (tid == 0) {
        unsigned long long mt = 0ull;
#pragma unroll
        for (int j = 0; j < 16; ++j) mt += s_m[j];
        double din = ldexp((double)mt, e8 ? ((int)e8 - 150) : -149);
        double tot = 0.0;
#pragma unroll
        for (int j = 0; j < NSB; ++j) tot += __ldcg(&g_psum[b * NSB + j]);
        tot += din + (double)kk4 * (double)__uint_as_float(T);
        g_neg_b[b] = (k > 0) ? tot : 0.0;
        __threadfence();
        s_fin = ((atomicAdd(&g_done, 1u) % B) == B - 1);
    }
    __syncthreads();
    if (!s_fin) return;

    // ---- global finalize (last batch to finish)
    double l = 0.0, cc2 = 0.0;
#pragma unroll
    for (int it = 0; it < NPART / 512; ++it) {
        l   += (double)g_part_l[tid + it * 512];
        cc2 += (double)g_part_c[tid + it * 512];
    }
#pragma unroll
    for (int dd = 16; dd > 0; dd >>= 1) {
        l   += __shfl_down_sync(0xffffffffu, l, dd);
        cc2 += __shfl_down_sync(0xffffffffu, cc2, dd);
    }
    __shared__ double s_l2[16], s_c2[16];
    if (lane == 0) { s_l2[wid] = l; s_c2[wid] = cc2; }
    __syncthreads();
    if (tid == 0) {
        double tl = 0.0, tc = 0.0;
#pragma unroll
        for (int j = 0; j < 16; ++j) { tl += s_l2[j]; tc += s_c2[j]; }
        double tneg = 0.0;
        int s = 0;
#pragma unroll
        for (int j = 0; j < B; ++j) {
            tneg += __ldcg(&g_neg_b[j]);
            s += g_num_pos[j];
        }
        double N = (double)s;
        if (N < 1.0) N = 1.0;
        out[0] = (float)(tl / N);
        out[1] = (float)((tc + tneg) / N);
    }
}

// ---------------- launch ----------------
extern "C" void kernel_launch(void* const* d_in, const int* in_sizes, int n_in,
                              void* d_out, int out_size) {
    const float* loc     = (const float*)d_in[0];
    const float* conf    = (const float*)d_in[1];
    const float* priors  = (const float*)d_in[2];
    const float* targets = (const float*)d_in[3];
    float* out = (float*)d_out;

    match_kernel<<<dim3(NCH, B), 256>>>(priors, targets);
    loss_kernel<<<dim3(LBLK, B), 256>>>(loc, conf, priors, targets);
    selA_kernel<<<dim3(NSB, B), 512>>>();
    selB_kernel<<<dim3(NSB, B), 512>>>(out);
}